// round 14
// baseline (speedup 1.0000x reference)
#include <cuda_runtime.h>
#include <cuda_fp16.h>
#include <stdint.h>
#include <math.h>

#define BATCH 16
#define CH    512
#define TT    1024
#define NHEAD 8
#define BHD   (BATCH * NHEAD)
#define HD    64

// Q pre-scale: hd^-0.5 (=0.125) * log2(e), so softmax runs in exp2 domain
#define QSCALE 0.1803368801111f

// ---------------- scratch ----------------------------------------------------
__device__ float g_mean[BATCH * 32];
__device__ float g_rstd[BATCH * 32];
__device__ __half g_Xh[(size_t)BATCH * TT * CH];
__device__ __half g_Whq[3 * CH * CH];
__device__ __half g_Whp[CH * CH];
__device__ __half g_Qh[(size_t)BHD * TT * HD];
__device__ __half g_Kh[(size_t)BHD * TT * HD];
__device__ __half g_Vh[(size_t)BHD * HD * TT];
__device__ __half g_hh[(size_t)BATCH * TT * CH];

// ---------------- helpers ------------------------------------------------------
__device__ __forceinline__ float ex2(float x) {
    float y;
    asm("ex2.approx.ftz.f32 %0, %1;" : "=f"(y) : "f"(x));
    return y;
}
__device__ __forceinline__ uint32_t h2ex2(uint32_t x) {
    uint32_t y;
    asm("ex2.approx.f16x2 %0, %1;" : "=r"(y) : "r"(x));
    return y;
}
__device__ __forceinline__ void mma16816(float c[4], const uint32_t a[4],
                                         uint32_t b0, uint32_t b1) {
    asm volatile(
        "mma.sync.aligned.m16n8k16.row.col.f32.f16.f16.f32 "
        "{%0,%1,%2,%3}, {%4,%5,%6,%7}, {%8,%9}, {%0,%1,%2,%3};"
        : "+f"(c[0]), "+f"(c[1]), "+f"(c[2]), "+f"(c[3])
        : "r"(a[0]), "r"(a[1]), "r"(a[2]), "r"(a[3]), "r"(b0), "r"(b1));
}
__device__ __forceinline__ void ldsm4(uint32_t r[4], uint32_t addr) {
    asm volatile("ldmatrix.sync.aligned.m8n8.x4.shared.b16 {%0,%1,%2,%3}, [%4];"
                 : "=r"(r[0]), "=r"(r[1]), "=r"(r[2]), "=r"(r[3]) : "r"(addr));
}
__device__ __forceinline__ uint32_t smem_u32(const void* p) {
    uint32_t a;
    asm("{ .reg .u64 t; cvta.to.shared.u64 t, %1; cvt.u32.u64 %0, t; }"
        : "=r"(a) : "l"(p));
    return a;
}
__device__ __forceinline__ void cp16(uint32_t d, const void* s) {
    asm volatile("cp.async.cg.shared.global [%0], [%1], 16;" :: "r"(d), "l"(s));
}
#define CP_COMMIT() asm volatile("cp.async.commit_group;" ::: "memory")
#define CP_WAIT(n)  asm volatile("cp.async.wait_group %0;" :: "n"(n) : "memory")

// ---------------- init: GroupNorm stats (blocks 0..511) + weight fp16 pack ------
__global__ void init_pack_kernel(const float* __restrict__ x,
                                 const float* __restrict__ qw,
                                 const float* __restrict__ pw) {
    if (blockIdx.x < 512) {
        const int bg = blockIdx.x;
        const float4* base = (const float4*)(x + (size_t)bg * 16 * TT);
        float s = 0.f, ss = 0.f;
        for (int i = threadIdx.x; i < 4096; i += 256) {
            float4 v = base[i];
            s  += v.x + v.y + v.z + v.w;
            ss += v.x*v.x + v.y*v.y + v.z*v.z + v.w*v.w;
        }
        #pragma unroll
        for (int o = 16; o; o >>= 1) {
            s  += __shfl_down_sync(0xffffffffu, s,  o);
            ss += __shfl_down_sync(0xffffffffu, ss, o);
        }
        __shared__ float sh[16];
        const int w = threadIdx.x >> 5, l = threadIdx.x & 31;
        if (l == 0) { sh[w] = s; sh[8 + w] = ss; }
        __syncthreads();
        if (threadIdx.x == 0) {
            float S = 0.f, SS = 0.f;
            #pragma unroll
            for (int i = 0; i < 8; i++) { S += sh[i]; SS += sh[8 + i]; }
            const float mean = S * (1.f / 16384.f);
            const float var  = SS * (1.f / 16384.f) - mean * mean;
            g_mean[bg] = mean;
            g_rstd[bg] = rsqrtf(var + 1e-5f);
        }
    } else {
        const int i = (blockIdx.x - 512) * 256 + threadIdx.x;
        const int NQ = 3 * CH * CH / 2;
        if (i < NQ) {
            float2 v = ((const float2*)qw)[i];
            __half2 h = __floats2half2_rn(v.x, v.y);
            ((uint32_t*)g_Whq)[i] = *(uint32_t*)&h;
        } else {
            const int j = i - NQ;
            float2 v = ((const float2*)pw)[j];
            __half2 h = __floats2half2_rn(v.x, v.y);
            ((uint32_t*)g_Whp)[j] = *(uint32_t*)&h;
        }
    }
}

// ---------------- x pack: GroupNorm + fp16 + transpose -> [b][t][c] -------------
__global__ void x_pack_kernel(const float* __restrict__ x,
                              const float* __restrict__ nw,
                              const float* __restrict__ nb) {
    __shared__ float tile[64][68];
    const int t0 = blockIdx.x * 64, c0 = blockIdx.y * 64, b = blockIdx.z;
    const int tid = threadIdx.x;
    const float* xb = x + (size_t)b * CH * TT;
    #pragma unroll
    for (int it = 0; it < 4; ++it) {
        const int f = tid + it * 256;
        const int cl = f >> 4, t4 = (f & 15) << 2;
        const int c = c0 + cl;
        float4 v = *(const float4*)(xb + (size_t)c * TT + t0 + t4);
        const int bg = (b << 5) + (c >> 4);
        const float w  = nw[c] * g_rstd[bg];
        const float bb = fmaf(-g_mean[bg], w, nb[c]);
        tile[cl][t4 + 0] = fmaf(v.x, w, bb);
        tile[cl][t4 + 1] = fmaf(v.y, w, bb);
        tile[cl][t4 + 2] = fmaf(v.z, w, bb);
        tile[cl][t4 + 3] = fmaf(v.w, w, bb);
    }
    __syncthreads();
    #pragma unroll
    for (int it = 0; it < 4; ++it) {
        const int f = tid + it * 256;
        const int tl = f >> 4, c4 = (f & 15) << 2;
        __half2 h0 = __floats2half2_rn(tile[c4 + 0][tl], tile[c4 + 1][tl]);
        __half2 h1 = __floats2half2_rn(tile[c4 + 2][tl], tile[c4 + 3][tl]);
        const size_t off = ((size_t)b * TT + t0 + tl) * CH + c0 + c4;
        *(uint2*)(g_Xh + off) = make_uint2(*(uint32_t*)&h0, *(uint32_t*)&h1);
    }
}

// ---------------- HMMA GEMM (1-term), 4-stage cp.async ring ----------------------
#define GP 40
#define GSB (128 * GP)
#define GSTG (2 * GSB * 2)
#define GEMM_SMEM (4 * GSTG)

template<bool IS_PROJ>
__global__ __launch_bounds__(256, 2)
void hgemm_kernel(const float* __restrict__ bias,
                  const float* __restrict__ resid,
                  float* __restrict__ outp) {
    extern __shared__ __half smh[];
    const uint32_t sb = smem_u32(smh);
    const int tid = threadIdx.x, lane = tid & 31, wid = tid >> 5;
    const int g = lane >> 2, tig = lane & 3;
    const int b = blockIdx.z;
    const int r0 = (IS_PROJ ? blockIdx.y : blockIdx.x) * 128;
    const int c0 = (IS_PROJ ? blockIdx.x : blockIdx.y) * 128;
    const int warp_m = wid >> 2, warp_n = wid & 3;

    const __half *pAh, *pBh;
    if (IS_PROJ) {
        pAh = g_Whp + (size_t)r0 * CH;
        pBh = g_hh + ((size_t)b * TT + c0) * CH;
    } else {
        pAh = g_Xh + ((size_t)b * TT + r0) * CH;
        pBh = g_Whq + (size_t)c0 * CH;
    }

    float acc[4][4][4];
    #pragma unroll
    for (int mi = 0; mi < 4; ++mi)
        #pragma unroll
        for (int ni = 0; ni < 4; ++ni)
            #pragma unroll
            for (int r = 0; r < 4; ++r) acc[mi][ni][r] = 0.f;

    const int aRow = warp_m * 64 + (lane & 15);
    const int aK   = (lane >> 4) << 3;
    const int bRow = warp_n * 32 + (lane & 7) + ((lane >> 4) << 3);
    const int bK   = ((lane >> 3) & 1) << 3;

    auto issue = [&](int ck) {
        const uint32_t st = sb + (ck & 3) * GSTG;
        const int k0 = ck * 32;
        #pragma unroll
        for (int it = 0; it < 2; ++it) {
            const int f = tid + it * 256;
            const int row = f >> 2, sg = (f & 3) << 3;
            const uint32_t da = st + (row * GP + sg) * 2;
            cp16(da,           pAh + (size_t)row * CH + k0 + sg);
            cp16(da + GSB * 2, pBh + (size_t)row * CH + k0 + sg);
        }
    };

    auto compute = [&](int ck) {
        const uint32_t st = sb + (ck & 3) * GSTG;
        const uint32_t aH = st, bH = st + GSB * 2;
        #pragma unroll
        for (int kk = 0; kk < 32; kk += 16) {
            uint32_t afh[4][4];
            #pragma unroll
            for (int mi = 0; mi < 4; ++mi)
                ldsm4(afh[mi], aH + ((aRow + mi * 16) * GP + kk + aK) * 2);
            #pragma unroll
            for (int nj = 0; nj < 2; ++nj) {
                uint32_t bfh[4];
                ldsm4(bfh, bH + ((bRow + nj * 16) * GP + kk + bK) * 2);
                #pragma unroll
                for (int mi = 0; mi < 4; ++mi) {
                    mma16816(acc[mi][nj * 2 + 0], afh[mi], bfh[0], bfh[1]);
                    mma16816(acc[mi][nj * 2 + 1], afh[mi], bfh[2], bfh[3]);
                }
            }
        }
    };

    issue(0); CP_COMMIT();
    issue(1); CP_COMMIT();
    issue(2); CP_COMMIT();
    for (int ck = 0; ck < 16; ++ck) {
        if (ck <= 13) CP_WAIT(2);
        else if (ck == 14) CP_WAIT(1);
        else CP_WAIT(0);
        __syncthreads();
        if (ck < 13) { issue(ck + 3); CP_COMMIT(); }
        compute(ck);
    }

    if (IS_PROJ) {
        const int mbase = r0 + warp_m * 64;
        const int nbase = c0 + warp_n * 32;
        const float* xres = resid + (size_t)b * CH * TT;
        float* ob = outp + (size_t)b * CH * TT;
        #pragma unroll
        for (int mi = 0; mi < 4; ++mi) {
            const int mA = mbase + mi * 16 + g;
            const int mB = mA + 8;
            const float biA = bias[mA], biB = bias[mB];
            #pragma unroll
            for (int ni = 0; ni < 4; ++ni) {
                const int t = nbase + ni * 8 + tig * 2;
                float2 v0, v1;
                v0.x = acc[mi][ni][0] + biA; v0.y = acc[mi][ni][1] + biA;
                v1.x = acc[mi][ni][2] + biB; v1.y = acc[mi][ni][3] + biB;
                float2 r0v = *(const float2*)(xres + (size_t)mA * TT + t);
                float2 r1v = *(const float2*)(xres + (size_t)mB * TT + t);
                v0.x += r0v.x; v0.y += r0v.y;
                v1.x += r1v.x; v1.y += r1v.y;
                *(float2*)(ob + (size_t)mA * TT + t) = v0;
                *(float2*)(ob + (size_t)mB * TT + t) = v1;
            }
        }
    } else {
        #pragma unroll
        for (int ni = 0; ni < 4; ++ni) {
            const int m = c0 + warp_n * 32 + ni * 8 + tig * 2;
            const int head = m / 192;
            const int rmod = m - head * 192;
            const int kind = rmod >> 6, c = rmod & 63;
            const int bh = b * NHEAD + head;
            const float b0v = bias[m], b1v = bias[m + 1];
            #pragma unroll
            for (int mi = 0; mi < 4; ++mi) {
                #pragma unroll
                for (int rr = 0; rr < 2; ++rr) {
                    const int t = r0 + warp_m * 64 + mi * 16 + g + rr * 8;
                    float v0 = acc[mi][ni][rr * 2 + 0] + b0v;
                    float v1 = acc[mi][ni][rr * 2 + 1] + b1v;
                    if (kind == 0) {
                        v0 *= QSCALE; v1 *= QSCALE;   // fold softmax scale + log2e
                        __half2 h2 = __floats2half2_rn(v0, v1);
                        *(__half2*)(g_Qh + ((size_t)bh * TT + t) * HD + c) = h2;
                    } else if (kind == 1) {
                        __half2 h2 = __floats2half2_rn(v0, v1);
                        *(__half2*)(g_Kh + ((size_t)bh * TT + t) * HD + c) = h2;
                    } else {
                        g_Vh[((size_t)bh * HD + c) * TT + t]     = __float2half_rn(v0);
                        g_Vh[((size_t)bh * HD + c + 1) * TT + t] = __float2half_rn(v1);
                    }
                }
            }
        }
    }
}

// ---------------- HMMA flash attention: KV block 128, 2-stage ring, exp2 domain --
// smem halves: Q @0 (128 x AP); stage s @9216 + s*17920: K 128xAP (+0),
//              V 64 x VP (+9216). AP=72, VP=136.
// Ring discipline (2 stages): compute(kb) -> __syncthreads -> issue(kb+2).
// P fragments alias sacc registers (sacc dead after exp) to stay under 128 regs.
#define AP 72
#define VP 136
#define ASTG (9216 + 8704)                  // 17920 halves per stage
#define ATTN_SMEM ((9216 + 2 * ASTG) * 2)   // 90112 B

__global__ __launch_bounds__(256, 2)
void attn_kernel() {
    extern __shared__ __half sa[];
    const uint32_t sb = smem_u32(sa);
    const int tid = threadIdx.x, lane = tid & 31, wid = tid >> 5;
    const int g = lane >> 2, tig = lane & 3;
    const int tblk = blockIdx.x, head = blockIdx.y, b = blockIdx.z;
    const int bh = b * NHEAD + head;
    const int t0 = tblk * 128;

    {   // Q: 128 rows x 64 halves (group 0)
        const __half* qh = g_Qh + ((size_t)bh * TT + t0) * HD;
        #pragma unroll
        for (int it = 0; it < 4; ++it) {
            const int f = tid + it * 256;
            const int row = f >> 3, sg = (f & 7) << 3;
            cp16(sb + (row * AP + sg) * 2, qh + (size_t)row * HD + sg);
        }
    }
    auto issueKV = [&](int kb) {
        const uint32_t st = sb + (9216 + (kb & 1) * ASTG) * 2;
        const int s0 = kb * 128;
        const __half* kh = g_Kh + ((size_t)bh * TT + s0) * HD;
        const __half* vh = g_Vh + (size_t)bh * HD * TT + s0;
        #pragma unroll
        for (int it = 0; it < 4; ++it) {
            const int f = tid + it * 256;
            const int kr = f >> 3, ksg = (f & 7) << 3;        // K: 128 rows x 64
            cp16(st + (kr * AP + ksg) * 2, kh + (size_t)kr * HD + ksg);
            const int vr = f >> 4, vsg = (f & 15) << 3;       // V: 64 rows x 128
            cp16(st + (9216 + vr * VP + vsg) * 2, vh + (size_t)vr * TT + vsg);
        }
    };

    issueKV(0); CP_COMMIT();
    issueKV(1); CP_COMMIT();

    const int qRow = wid * 16 + (lane & 15);
    const int qK   = (lane >> 4) << 3;
    const int nRow = (lane & 7) + ((lane >> 4) << 3);
    const int nK   = ((lane >> 3) & 1) << 3;

    float m_i0 = -1e30f, m_i1 = -1e30f, l_i0 = 0.f, l_i1 = 0.f;
    float oacc[8][4];
    #pragma unroll
    for (int nc = 0; nc < 8; ++nc)
        #pragma unroll
        for (int r = 0; r < 4; ++r) oacc[nc][r] = 0.f;

    for (int kb = 0; kb < 8; ++kb) {
        if (kb < 7) CP_WAIT(1); else CP_WAIT(0);
        __syncthreads();
        const uint32_t st = sb + (9216 + (kb & 1) * ASTG) * 2;

        // ---- S = Q K^T over 128 s-cols (Q pre-scaled into exp2 domain)
        float sacc[16][4];
        #pragma unroll
        for (int ni = 0; ni < 16; ++ni)
            #pragma unroll
            for (int r = 0; r < 4; ++r) sacc[ni][r] = 0.f;

        #pragma unroll
        for (int ks = 0; ks < 4; ++ks) {
            uint32_t ah[4];
            ldsm4(ah, sb + ((qRow * AP) + ks * 16 + qK) * 2);
            #pragma unroll
            for (int nj = 0; nj < 8; ++nj) {
                uint32_t kb4[4];
                ldsm4(kb4, st + (((nj * 16 + nRow) * AP) + ks * 16 + nK) * 2);
                mma16816(sacc[nj * 2 + 0], ah, kb4[0], kb4[1]);
                mma16816(sacc[nj * 2 + 1], ah, kb4[2], kb4[3]);
            }
        }

        // ---- online softmax in exp2 domain (rows g and g+8)
        float mx0 = -1e30f, mx1 = -1e30f;
        #pragma unroll
        for (int ni = 0; ni < 16; ++ni) {
            mx0 = fmaxf(mx0, fmaxf(sacc[ni][0], sacc[ni][1]));
            mx1 = fmaxf(mx1, fmaxf(sacc[ni][2], sacc[ni][3]));
        }
        mx0 = fmaxf(mx0, __shfl_xor_sync(0xffffffffu, mx0, 1));
        mx0 = fmaxf(mx0, __shfl_xor_sync(0xffffffffu, mx0, 2));
        mx1 = fmaxf(mx1, __shfl_xor_sync(0xffffffffu, mx1, 1));
        mx1 = fmaxf(mx1, __shfl_xor_sync(0xffffffffu, mx1, 2));
        const float mn0 = fmaxf(m_i0, mx0), mn1 = fmaxf(m_i1, mx1);
        const float c0 = ex2(m_i0 - mn0), c1 = ex2(m_i1 - mn1);
        m_i0 = mn0; m_i1 = mn1;
        float rs0 = 0.f, rs1 = 0.f;
        // exp via f16x2 MUFU; P fragments overwrite sacc[ni][0..1] (dead values)
        #pragma unroll
        for (int ni = 0; ni < 16; ++ni) {
            __half2 x01 = __floats2half2_rn(sacc[ni][0] - mn0, sacc[ni][1] - mn0);
            __half2 x23 = __floats2half2_rn(sacc[ni][2] - mn1, sacc[ni][3] - mn1);
            const uint32_t e01 = h2ex2(*reinterpret_cast<uint32_t*>(&x01));
            const uint32_t e23 = h2ex2(*reinterpret_cast<uint32_t*>(&x23));
            float2 f01 = __half22float2(*reinterpret_cast<const __half2*>(&e01));
            float2 f23 = __half22float2(*reinterpret_cast<const __half2*>(&e23));
            rs0 += f01.x + f01.y;
            rs1 += f23.x + f23.y;
            sacc[ni][0] = __uint_as_float(e01);
            sacc[ni][1] = __uint_as_float(e23);
        }
        rs0 += __shfl_xor_sync(0xffffffffu, rs0, 1);
        rs0 += __shfl_xor_sync(0xffffffffu, rs0, 2);
        rs1 += __shfl_xor_sync(0xffffffffu, rs1, 1);
        rs1 += __shfl_xor_sync(0xffffffffu, rs1, 2);
        l_i0 = l_i0 * c0 + rs0;
        l_i1 = l_i1 * c1 + rs1;
        #pragma unroll
        for (int nc = 0; nc < 8; ++nc) {
            oacc[nc][0] *= c0; oacc[nc][1] *= c0;
            oacc[nc][2] *= c1; oacc[nc][3] *= c1;
        }

        // ---- O += P Vh^T (s-dim 128 = 8 k-steps of 16); P lives in sacc[..][0..1]
        #pragma unroll
        for (int ks = 0; ks < 8; ++ks) {
            const uint32_t pa[4] = {
                __float_as_uint(sacc[2 * ks][0]),     __float_as_uint(sacc[2 * ks][1]),
                __float_as_uint(sacc[2 * ks + 1][0]), __float_as_uint(sacc[2 * ks + 1][1]) };
            #pragma unroll
            for (int nj = 0; nj < 4; ++nj) {
                uint32_t vb4[4];
                ldsm4(vb4, st + ((9216 + (nj * 16 + nRow) * VP) + ks * 16 + nK) * 2);
                mma16816(oacc[nj * 2 + 0], pa, vb4[0], vb4[1]);
                mma16816(oacc[nj * 2 + 1], pa, vb4[2], vb4[3]);
            }
        }

        // all reads of stage (kb & 1) complete before it is overwritten
        __syncthreads();
        if (kb < 6) { issueKV(kb + 2); CP_COMMIT(); }
    }

    // ---- epilogue: store fp16 h, [b][t][c]
    const float inv0 = 1.f / l_i0, inv1 = 1.f / l_i1;
    #pragma unroll
    for (int nc = 0; nc < 8; ++nc) {
        const size_t off0 = ((size_t)b * TT + t0 + wid * 16 + g) * CH
                          + head * 64 + nc * 8 + tig * 2;
        __half2 h0 = __floats2half2_rn(oacc[nc][0] * inv0, oacc[nc][1] * inv0);
        *(__half2*)(g_hh + off0) = h0;
        const size_t off1 = off0 + (size_t)8 * CH;
        __half2 h1 = __floats2half2_rn(oacc[nc][2] * inv1, oacc[nc][3] * inv1);
        *(__half2*)(g_hh + off1) = h1;
    }
}

// ---------------- launch ----------------------------------------------------------
extern "C" void kernel_launch(void* const* d_in, const int* in_sizes, int n_in,
                              void* d_out, int out_size) {
    const float* x    = (const float*)d_in[0];
    const float* nw   = (const float*)d_in[1];
    const float* nb   = (const float*)d_in[2];
    const float* qkvw = (const float*)d_in[3];
    const float* qkvb = (const float*)d_in[4];
    const float* pw   = (const float*)d_in[5];
    const float* pb   = (const float*)d_in[6];
    float* out = (float*)d_out;

    cudaFuncSetAttribute(hgemm_kernel<false>,
                         cudaFuncAttributeMaxDynamicSharedMemorySize, GEMM_SMEM);
    cudaFuncSetAttribute(hgemm_kernel<true>,
                         cudaFuncAttributeMaxDynamicSharedMemorySize, GEMM_SMEM);
    cudaFuncSetAttribute(attn_kernel,
                         cudaFuncAttributeMaxDynamicSharedMemorySize, ATTN_SMEM);

    init_pack_kernel<<<512 + 2048, 256>>>(x, qkvw, pw);
    x_pack_kernel<<<dim3(16, 8, 16), 256>>>(x, nw, nb);
    hgemm_kernel<false><<<dim3(8, 12, BATCH), 256, GEMM_SMEM>>>(qkvb, nullptr, nullptr);
    attn_kernel<<<dim3(8, NHEAD, BATCH), 256, ATTN_SMEM>>>();
    hgemm_kernel<true><<<dim3(8, 4, BATCH), 256, GEMM_SMEM>>>(pb, x, out);
}

// round 15
// speedup vs baseline: 1.0390x; 1.0390x over previous
#include <cuda_runtime.h>
#include <cuda_fp16.h>
#include <stdint.h>
#include <math.h>

#define BATCH 16
#define CH    512
#define TT    1024
#define NHEAD 8
#define BHD   (BATCH * NHEAD)
#define HD    64

// Q pre-scale: hd^-0.5 (=0.125) * log2(e), so softmax runs in exp2 domain
#define QSCALE 0.1803368801111f
// fp16 {1.0, 1.0} — B fragment of an all-ones tile
#define ONES16 0x3C003C00u

// ---------------- scratch ----------------------------------------------------
__device__ float g_mean[BATCH * 32];
__device__ float g_rstd[BATCH * 32];
__device__ __half g_Xh[(size_t)BATCH * TT * CH];
__device__ __half g_Whq[3 * CH * CH];
__device__ __half g_Whp[CH * CH];
__device__ __half g_Qh[(size_t)BHD * TT * HD];
__device__ __half g_Kh[(size_t)BHD * TT * HD];
__device__ __half g_Vh[(size_t)BHD * HD * TT];
__device__ __half g_hh[(size_t)BATCH * TT * CH];

// ---------------- helpers ------------------------------------------------------
__device__ __forceinline__ float ex2(float x) {
    float y;
    asm("ex2.approx.ftz.f32 %0, %1;" : "=f"(y) : "f"(x));
    return y;
}
__device__ __forceinline__ void mma16816(float c[4], const uint32_t a[4],
                                         uint32_t b0, uint32_t b1) {
    asm volatile(
        "mma.sync.aligned.m16n8k16.row.col.f32.f16.f16.f32 "
        "{%0,%1,%2,%3}, {%4,%5,%6,%7}, {%8,%9}, {%0,%1,%2,%3};"
        : "+f"(c[0]), "+f"(c[1]), "+f"(c[2]), "+f"(c[3])
        : "r"(a[0]), "r"(a[1]), "r"(a[2]), "r"(a[3]), "r"(b0), "r"(b1));
}
__device__ __forceinline__ void ldsm4(uint32_t r[4], uint32_t addr) {
    asm volatile("ldmatrix.sync.aligned.m8n8.x4.shared.b16 {%0,%1,%2,%3}, [%4];"
                 : "=r"(r[0]), "=r"(r[1]), "=r"(r[2]), "=r"(r[3]) : "r"(addr));
}
__device__ __forceinline__ uint32_t smem_u32(const void* p) {
    uint32_t a;
    asm("{ .reg .u64 t; cvta.to.shared.u64 t, %1; cvt.u32.u64 %0, t; }"
        : "=r"(a) : "l"(p));
    return a;
}
__device__ __forceinline__ void cp16(uint32_t d, const void* s) {
    asm volatile("cp.async.cg.shared.global [%0], [%1], 16;" :: "r"(d), "l"(s));
}
#define CP_COMMIT() asm volatile("cp.async.commit_group;" ::: "memory")
#define CP_WAIT(n)  asm volatile("cp.async.wait_group %0;" :: "n"(n) : "memory")

// ---------------- init: GroupNorm stats (blocks 0..511) + weight fp16 pack ------
__global__ void init_pack_kernel(const float* __restrict__ x,
                                 const float* __restrict__ qw,
                                 const float* __restrict__ pw) {
    if (blockIdx.x < 512) {
        const int bg = blockIdx.x;
        const float4* base = (const float4*)(x + (size_t)bg * 16 * TT);
        float s = 0.f, ss = 0.f;
        for (int i = threadIdx.x; i < 4096; i += 256) {
            float4 v = base[i];
            s  += v.x + v.y + v.z + v.w;
            ss += v.x*v.x + v.y*v.y + v.z*v.z + v.w*v.w;
        }
        #pragma unroll
        for (int o = 16; o; o >>= 1) {
            s  += __shfl_down_sync(0xffffffffu, s,  o);
            ss += __shfl_down_sync(0xffffffffu, ss, o);
        }
        __shared__ float sh[16];
        const int w = threadIdx.x >> 5, l = threadIdx.x & 31;
        if (l == 0) { sh[w] = s; sh[8 + w] = ss; }
        __syncthreads();
        if (threadIdx.x == 0) {
            float S = 0.f, SS = 0.f;
            #pragma unroll
            for (int i = 0; i < 8; i++) { S += sh[i]; SS += sh[8 + i]; }
            const float mean = S * (1.f / 16384.f);
            const float var  = SS * (1.f / 16384.f) - mean * mean;
            g_mean[bg] = mean;
            g_rstd[bg] = rsqrtf(var + 1e-5f);
        }
    } else {
        const int i = (blockIdx.x - 512) * 256 + threadIdx.x;
        const int NQ = 3 * CH * CH / 2;
        if (i < NQ) {
            float2 v = ((const float2*)qw)[i];
            __half2 h = __floats2half2_rn(v.x, v.y);
            ((uint32_t*)g_Whq)[i] = *(uint32_t*)&h;
        } else {
            const int j = i - NQ;
            float2 v = ((const float2*)pw)[j];
            __half2 h = __floats2half2_rn(v.x, v.y);
            ((uint32_t*)g_Whp)[j] = *(uint32_t*)&h;
        }
    }
}

// ---------------- x pack: GroupNorm + fp16 + transpose -> [b][t][c] -------------
__global__ void x_pack_kernel(const float* __restrict__ x,
                              const float* __restrict__ nw,
                              const float* __restrict__ nb) {
    __shared__ float tile[64][68];
    const int t0 = blockIdx.x * 64, c0 = blockIdx.y * 64, b = blockIdx.z;
    const int tid = threadIdx.x;
    const float* xb = x + (size_t)b * CH * TT;
    #pragma unroll
    for (int it = 0; it < 4; ++it) {
        const int f = tid + it * 256;
        const int cl = f >> 4, t4 = (f & 15) << 2;
        const int c = c0 + cl;
        float4 v = *(const float4*)(xb + (size_t)c * TT + t0 + t4);
        const int bg = (b << 5) + (c >> 4);
        const float w  = nw[c] * g_rstd[bg];
        const float bb = fmaf(-g_mean[bg], w, nb[c]);
        tile[cl][t4 + 0] = fmaf(v.x, w, bb);
        tile[cl][t4 + 1] = fmaf(v.y, w, bb);
        tile[cl][t4 + 2] = fmaf(v.z, w, bb);
        tile[cl][t4 + 3] = fmaf(v.w, w, bb);
    }
    __syncthreads();
    #pragma unroll
    for (int it = 0; it < 4; ++it) {
        const int f = tid + it * 256;
        const int tl = f >> 4, c4 = (f & 15) << 2;
        __half2 h0 = __floats2half2_rn(tile[c4 + 0][tl], tile[c4 + 1][tl]);
        __half2 h1 = __floats2half2_rn(tile[c4 + 2][tl], tile[c4 + 3][tl]);
        const size_t off = ((size_t)b * TT + t0 + tl) * CH + c0 + c4;
        *(uint2*)(g_Xh + off) = make_uint2(*(uint32_t*)&h0, *(uint32_t*)&h1);
    }
}

// ---------------- HMMA GEMM (1-term), 4-stage cp.async ring ----------------------
#define GP 40
#define GSB (128 * GP)
#define GSTG (2 * GSB * 2)
#define GEMM_SMEM (4 * GSTG)

template<bool IS_PROJ>
__global__ __launch_bounds__(256, 2)
void hgemm_kernel(const float* __restrict__ bias,
                  const float* __restrict__ resid,
                  float* __restrict__ outp) {
    extern __shared__ __half smh[];
    const uint32_t sb = smem_u32(smh);
    const int tid = threadIdx.x, lane = tid & 31, wid = tid >> 5;
    const int g = lane >> 2, tig = lane & 3;
    const int b = blockIdx.z;
    const int r0 = (IS_PROJ ? blockIdx.y : blockIdx.x) * 128;
    const int c0 = (IS_PROJ ? blockIdx.x : blockIdx.y) * 128;
    const int warp_m = wid >> 2, warp_n = wid & 3;

    const __half *pAh, *pBh;
    if (IS_PROJ) {
        pAh = g_Whp + (size_t)r0 * CH;
        pBh = g_hh + ((size_t)b * TT + c0) * CH;
    } else {
        pAh = g_Xh + ((size_t)b * TT + r0) * CH;
        pBh = g_Whq + (size_t)c0 * CH;
    }

    float acc[4][4][4];
    #pragma unroll
    for (int mi = 0; mi < 4; ++mi)
        #pragma unroll
        for (int ni = 0; ni < 4; ++ni)
            #pragma unroll
            for (int r = 0; r < 4; ++r) acc[mi][ni][r] = 0.f;

    const int aRow = warp_m * 64 + (lane & 15);
    const int aK   = (lane >> 4) << 3;
    const int bRow = warp_n * 32 + (lane & 7) + ((lane >> 4) << 3);
    const int bK   = ((lane >> 3) & 1) << 3;

    auto issue = [&](int ck) {
        const uint32_t st = sb + (ck & 3) * GSTG;
        const int k0 = ck * 32;
        #pragma unroll
        for (int it = 0; it < 2; ++it) {
            const int f = tid + it * 256;
            const int row = f >> 2, sg = (f & 3) << 3;
            const uint32_t da = st + (row * GP + sg) * 2;
            cp16(da,           pAh + (size_t)row * CH + k0 + sg);
            cp16(da + GSB * 2, pBh + (size_t)row * CH + k0 + sg);
        }
    };

    auto compute = [&](int ck) {
        const uint32_t st = sb + (ck & 3) * GSTG;
        const uint32_t aH = st, bH = st + GSB * 2;
        #pragma unroll
        for (int kk = 0; kk < 32; kk += 16) {
            uint32_t afh[4][4];
            #pragma unroll
            for (int mi = 0; mi < 4; ++mi)
                ldsm4(afh[mi], aH + ((aRow + mi * 16) * GP + kk + aK) * 2);
            #pragma unroll
            for (int nj = 0; nj < 2; ++nj) {
                uint32_t bfh[4];
                ldsm4(bfh, bH + ((bRow + nj * 16) * GP + kk + bK) * 2);
                #pragma unroll
                for (int mi = 0; mi < 4; ++mi) {
                    mma16816(acc[mi][nj * 2 + 0], afh[mi], bfh[0], bfh[1]);
                    mma16816(acc[mi][nj * 2 + 1], afh[mi], bfh[2], bfh[3]);
                }
            }
        }
    };

    issue(0); CP_COMMIT();
    issue(1); CP_COMMIT();
    issue(2); CP_COMMIT();
    for (int ck = 0; ck < 16; ++ck) {
        if (ck <= 13) CP_WAIT(2);
        else if (ck == 14) CP_WAIT(1);
        else CP_WAIT(0);
        __syncthreads();
        if (ck < 13) { issue(ck + 3); CP_COMMIT(); }
        compute(ck);
    }

    if (IS_PROJ) {
        const int mbase = r0 + warp_m * 64;
        const int nbase = c0 + warp_n * 32;
        const float* xres = resid + (size_t)b * CH * TT;
        float* ob = outp + (size_t)b * CH * TT;
        #pragma unroll
        for (int mi = 0; mi < 4; ++mi) {
            const int mA = mbase + mi * 16 + g;
            const int mB = mA + 8;
            const float biA = bias[mA], biB = bias[mB];
            #pragma unroll
            for (int ni = 0; ni < 4; ++ni) {
                const int t = nbase + ni * 8 + tig * 2;
                float2 v0, v1;
                v0.x = acc[mi][ni][0] + biA; v0.y = acc[mi][ni][1] + biA;
                v1.x = acc[mi][ni][2] + biB; v1.y = acc[mi][ni][3] + biB;
                float2 r0v = *(const float2*)(xres + (size_t)mA * TT + t);
                float2 r1v = *(const float2*)(xres + (size_t)mB * TT + t);
                v0.x += r0v.x; v0.y += r0v.y;
                v1.x += r1v.x; v1.y += r1v.y;
                *(float2*)(ob + (size_t)mA * TT + t) = v0;
                *(float2*)(ob + (size_t)mB * TT + t) = v1;
            }
        }
    } else {
        #pragma unroll
        for (int ni = 0; ni < 4; ++ni) {
            const int m = c0 + warp_n * 32 + ni * 8 + tig * 2;
            const int head = m / 192;
            const int rmod = m - head * 192;
            const int kind = rmod >> 6, c = rmod & 63;
            const int bh = b * NHEAD + head;
            const float b0v = bias[m], b1v = bias[m + 1];
            #pragma unroll
            for (int mi = 0; mi < 4; ++mi) {
                #pragma unroll
                for (int rr = 0; rr < 2; ++rr) {
                    const int t = r0 + warp_m * 64 + mi * 16 + g + rr * 8;
                    float v0 = acc[mi][ni][rr * 2 + 0] + b0v;
                    float v1 = acc[mi][ni][rr * 2 + 1] + b1v;
                    if (kind == 0) {
                        v0 *= QSCALE; v1 *= QSCALE;   // fold softmax scale + log2e
                        __half2 h2 = __floats2half2_rn(v0, v1);
                        *(__half2*)(g_Qh + ((size_t)bh * TT + t) * HD + c) = h2;
                    } else if (kind == 1) {
                        __half2 h2 = __floats2half2_rn(v0, v1);
                        *(__half2*)(g_Kh + ((size_t)bh * TT + t) * HD + c) = h2;
                    } else {
                        g_Vh[((size_t)bh * HD + c) * TT + t]     = __float2half_rn(v0);
                        g_Vh[((size_t)bh * HD + c + 1) * TT + t] = __float2half_rn(v1);
                    }
                }
            }
        }
    }
}

// ---------------- HMMA flash attention: KV block 128, 2-stage ring, exp2 domain --
// smem halves: Q @0 (128 x AP); stage s @9216 + s*17920: K 128xAP (+0),
//              V 64 x VP (+9216). AP=72, VP=136.
// Ring discipline (2 stages): compute(kb) -> __syncthreads -> issue(kb+2).
// Row-sum l is accumulated by an extra MMA against a constant all-ones B
// fragment (ONES16) and rescaled like oacc -> no rs adds/shuffles in softmax.
#define AP 72
#define VP 136
#define ASTG (9216 + 8704)                  // 17920 halves per stage
#define ATTN_SMEM ((9216 + 2 * ASTG) * 2)   // 90112 B

__global__ __launch_bounds__(256, 2)
void attn_kernel() {
    extern __shared__ __half sa[];
    const uint32_t sb = smem_u32(sa);
    const int tid = threadIdx.x, lane = tid & 31, wid = tid >> 5;
    const int g = lane >> 2, tig = lane & 3;
    const int tblk = blockIdx.x, head = blockIdx.y, b = blockIdx.z;
    const int bh = b * NHEAD + head;
    const int t0 = tblk * 128;

    {   // Q: 128 rows x 64 halves (group 0)
        const __half* qh = g_Qh + ((size_t)bh * TT + t0) * HD;
        #pragma unroll
        for (int it = 0; it < 4; ++it) {
            const int f = tid + it * 256;
            const int row = f >> 3, sg = (f & 7) << 3;
            cp16(sb + (row * AP + sg) * 2, qh + (size_t)row * HD + sg);
        }
    }
    auto issueKV = [&](int kb) {
        const uint32_t st = sb + (9216 + (kb & 1) * ASTG) * 2;
        const int s0 = kb * 128;
        const __half* kh = g_Kh + ((size_t)bh * TT + s0) * HD;
        const __half* vh = g_Vh + (size_t)bh * HD * TT + s0;
        #pragma unroll
        for (int it = 0; it < 4; ++it) {
            const int f = tid + it * 256;
            const int kr = f >> 3, ksg = (f & 7) << 3;        // K: 128 rows x 64
            cp16(st + (kr * AP + ksg) * 2, kh + (size_t)kr * HD + ksg);
            const int vr = f >> 4, vsg = (f & 15) << 3;       // V: 64 rows x 128
            cp16(st + (9216 + vr * VP + vsg) * 2, vh + (size_t)vr * TT + vsg);
        }
    };

    issueKV(0); CP_COMMIT();
    issueKV(1); CP_COMMIT();

    const int qRow = wid * 16 + (lane & 15);
    const int qK   = (lane >> 4) << 3;
    const int nRow = (lane & 7) + ((lane >> 4) << 3);
    const int nK   = ((lane >> 3) & 1) << 3;

    float m_i0 = -1e30f, m_i1 = -1e30f;
    float oacc[8][4], lacc[4];
    #pragma unroll
    for (int nc = 0; nc < 8; ++nc)
        #pragma unroll
        for (int r = 0; r < 4; ++r) oacc[nc][r] = 0.f;
    #pragma unroll
    for (int r = 0; r < 4; ++r) lacc[r] = 0.f;

    for (int kb = 0; kb < 8; ++kb) {
        if (kb < 7) CP_WAIT(1); else CP_WAIT(0);
        __syncthreads();
        const uint32_t st = sb + (9216 + (kb & 1) * ASTG) * 2;

        // ---- S = Q K^T over 128 s-cols (Q pre-scaled into exp2 domain)
        float sacc[16][4];
        #pragma unroll
        for (int ni = 0; ni < 16; ++ni)
            #pragma unroll
            for (int r = 0; r < 4; ++r) sacc[ni][r] = 0.f;

        #pragma unroll
        for (int ks = 0; ks < 4; ++ks) {
            uint32_t ah[4];
            ldsm4(ah, sb + ((qRow * AP) + ks * 16 + qK) * 2);
            #pragma unroll
            for (int nj = 0; nj < 8; ++nj) {
                uint32_t kb4[4];
                ldsm4(kb4, st + (((nj * 16 + nRow) * AP) + ks * 16 + nK) * 2);
                mma16816(sacc[nj * 2 + 0], ah, kb4[0], kb4[1]);
                mma16816(sacc[nj * 2 + 1], ah, kb4[2], kb4[3]);
            }
        }

        // ---- online softmax in exp2 domain (rows g and g+8)
        float mx0 = -1e30f, mx1 = -1e30f;
        #pragma unroll
        for (int ni = 0; ni < 16; ++ni) {
            mx0 = fmaxf(mx0, fmaxf(sacc[ni][0], sacc[ni][1]));
            mx1 = fmaxf(mx1, fmaxf(sacc[ni][2], sacc[ni][3]));
        }
        mx0 = fmaxf(mx0, __shfl_xor_sync(0xffffffffu, mx0, 1));
        mx0 = fmaxf(mx0, __shfl_xor_sync(0xffffffffu, mx0, 2));
        mx1 = fmaxf(mx1, __shfl_xor_sync(0xffffffffu, mx1, 1));
        mx1 = fmaxf(mx1, __shfl_xor_sync(0xffffffffu, mx1, 2));
        const float mn0 = fmaxf(m_i0, mx0), mn1 = fmaxf(m_i1, mx1);
        const float c0 = ex2(m_i0 - mn0), c1 = ex2(m_i1 - mn1);
        m_i0 = mn0; m_i1 = mn1;
        // exp (fp32 MUFU) -> packed P fragments aliased into sacc[ni][0..1]
        #pragma unroll
        for (int ni = 0; ni < 16; ++ni) {
            const float p0 = ex2(sacc[ni][0] - mn0);
            const float p1 = ex2(sacc[ni][1] - mn0);
            const float p2 = ex2(sacc[ni][2] - mn1);
            const float p3 = ex2(sacc[ni][3] - mn1);
            __half2 h0 = __floats2half2_rn(p0, p1);
            __half2 h1 = __floats2half2_rn(p2, p3);
            sacc[ni][0] = __uint_as_float(*reinterpret_cast<uint32_t*>(&h0));
            sacc[ni][1] = __uint_as_float(*reinterpret_cast<uint32_t*>(&h1));
        }
        #pragma unroll
        for (int nc = 0; nc < 8; ++nc) {
            oacc[nc][0] *= c0; oacc[nc][1] *= c0;
            oacc[nc][2] *= c1; oacc[nc][3] *= c1;
        }
        lacc[0] *= c0; lacc[1] *= c0; lacc[2] *= c1; lacc[3] *= c1;

        // ---- O += P Vh^T, l += P·1 (s-dim 128 = 8 k-steps of 16)
        #pragma unroll
        for (int ks = 0; ks < 8; ++ks) {
            const uint32_t pa[4] = {
                __float_as_uint(sacc[2 * ks][0]),     __float_as_uint(sacc[2 * ks][1]),
                __float_as_uint(sacc[2 * ks + 1][0]), __float_as_uint(sacc[2 * ks + 1][1]) };
            #pragma unroll
            for (int nj = 0; nj < 4; ++nj) {
                uint32_t vb4[4];
                ldsm4(vb4, st + ((9216 + (nj * 16 + nRow) * VP) + ks * 16 + nK) * 2);
                mma16816(oacc[nj * 2 + 0], pa, vb4[0], vb4[1]);
                mma16816(oacc[nj * 2 + 1], pa, vb4[2], vb4[3]);
            }
            mma16816(lacc, pa, ONES16, ONES16);   // row sums
        }

        // all reads of stage (kb & 1) complete before it is overwritten
        __syncthreads();
        if (kb < 6) { issueKV(kb + 2); CP_COMMIT(); }
    }

    // ---- epilogue: store fp16 h, [b][t][c]
    const float inv0 = 1.f / lacc[0], inv1 = 1.f / lacc[2];
    #pragma unroll
    for (int nc = 0; nc < 8; ++nc) {
        const size_t off0 = ((size_t)b * TT + t0 + wid * 16 + g) * CH
                          + head * 64 + nc * 8 + tig * 2;
        __half2 h0 = __floats2half2_rn(oacc[nc][0] * inv0, oacc[nc][1] * inv0);
        *(__half2*)(g_hh + off0) = h0;
        const size_t off1 = off0 + (size_t)8 * CH;
        __half2 h1 = __floats2half2_rn(oacc[nc][2] * inv1, oacc[nc][3] * inv1);
        *(__half2*)(g_hh + off1) = h1;
    }
}

// ---------------- launch ----------------------------------------------------------
extern "C" void kernel_launch(void* const* d_in, const int* in_sizes, int n_in,
                              void* d_out, int out_size) {
    const float* x    = (const float*)d_in[0];
    const float* nw   = (const float*)d_in[1];
    const float* nb   = (const float*)d_in[2];
    const float* qkvw = (const float*)d_in[3];
    const float* qkvb = (const float*)d_in[4];
    const float* pw   = (const float*)d_in[5];
    const float* pb   = (const float*)d_in[6];
    float* out = (float*)d_out;

    cudaFuncSetAttribute(hgemm_kernel<false>,
                         cudaFuncAttributeMaxDynamicSharedMemorySize, GEMM_SMEM);
    cudaFuncSetAttribute(hgemm_kernel<true>,
                         cudaFuncAttributeMaxDynamicSharedMemorySize, GEMM_SMEM);
    cudaFuncSetAttribute(attn_kernel,
                         cudaFuncAttributeMaxDynamicSharedMemorySize, ATTN_SMEM);

    init_pack_kernel<<<512 + 2048, 256>>>(x, qkvw, pw);
    x_pack_kernel<<<dim3(16, 8, 16), 256>>>(x, nw, nb);
    hgemm_kernel<false><<<dim3(8, 12, BATCH), 256, GEMM_SMEM>>>(qkvb, nullptr, nullptr);
    attn_kernel<<<dim3(8, NHEAD, BATCH), 256, ATTN_SMEM>>>();
    hgemm_kernel<true><<<dim3(8, 4, BATCH), 256, GEMM_SMEM>>>(pb, x, out);
}

// round 16
// speedup vs baseline: 1.0425x; 1.0034x over previous
#include <cuda_runtime.h>
#include <cuda_fp16.h>
#include <stdint.h>
#include <math.h>

#define BATCH 16
#define CH    512
#define TT    1024
#define NHEAD 8
#define BHD   (BATCH * NHEAD)
#define HD    64

// Q pre-scale: hd^-0.5 (=0.125) * log2(e), so softmax runs in exp2 domain
#define QSCALE 0.1803368801111f
// fp16 {1.0, 1.0} — B fragment of an all-ones tile
#define ONES16 0x3C003C00u

// ---------------- scratch ----------------------------------------------------
__device__ float g_mean[BATCH * 32];
__device__ float g_rstd[BATCH * 32];
__device__ __half g_Xh[(size_t)BATCH * TT * CH];
__device__ __half g_Whq[3 * CH * CH];
__device__ __half g_Whp[CH * CH];
__device__ __half g_Qh[(size_t)BHD * TT * HD];
__device__ __half g_Kh[(size_t)BHD * TT * HD];
__device__ __half g_Vh[(size_t)BHD * HD * TT];
__device__ __half g_hh[(size_t)BATCH * TT * CH];

// ---------------- helpers ------------------------------------------------------
__device__ __forceinline__ float ex2(float x) {
    float y;
    asm("ex2.approx.ftz.f32 %0, %1;" : "=f"(y) : "f"(x));
    return y;
}
__device__ __forceinline__ void mma16816(float c[4], const uint32_t a[4],
                                         uint32_t b0, uint32_t b1) {
    asm volatile(
        "mma.sync.aligned.m16n8k16.row.col.f32.f16.f16.f32 "
        "{%0,%1,%2,%3}, {%4,%5,%6,%7}, {%8,%9}, {%0,%1,%2,%3};"
        : "+f"(c[0]), "+f"(c[1]), "+f"(c[2]), "+f"(c[3])
        : "r"(a[0]), "r"(a[1]), "r"(a[2]), "r"(a[3]), "r"(b0), "r"(b1));
}
__device__ __forceinline__ void ldsm4(uint32_t r[4], uint32_t addr) {
    asm volatile("ldmatrix.sync.aligned.m8n8.x4.shared.b16 {%0,%1,%2,%3}, [%4];"
                 : "=r"(r[0]), "=r"(r[1]), "=r"(r[2]), "=r"(r[3]) : "r"(addr));
}
__device__ __forceinline__ uint32_t smem_u32(const void* p) {
    uint32_t a;
    asm("{ .reg .u64 t; cvta.to.shared.u64 t, %1; cvt.u32.u64 %0, t; }"
        : "=r"(a) : "l"(p));
    return a;
}
__device__ __forceinline__ void cp16(uint32_t d, const void* s) {
    asm volatile("cp.async.cg.shared.global [%0], [%1], 16;" :: "r"(d), "l"(s));
}
#define CP_COMMIT() asm volatile("cp.async.commit_group;" ::: "memory")
#define CP_WAIT(n)  asm volatile("cp.async.wait_group %0;" :: "n"(n) : "memory")

// ---------------- init: GroupNorm stats (blocks 0..511) + weight fp16 pack ------
__global__ void init_pack_kernel(const float* __restrict__ x,
                                 const float* __restrict__ qw,
                                 const float* __restrict__ pw) {
    if (blockIdx.x < 512) {
        const int bg = blockIdx.x;
        const float4* base = (const float4*)(x + (size_t)bg * 16 * TT);
        float s = 0.f, ss = 0.f;
        for (int i = threadIdx.x; i < 4096; i += 256) {
            float4 v = base[i];
            s  += v.x + v.y + v.z + v.w;
            ss += v.x*v.x + v.y*v.y + v.z*v.z + v.w*v.w;
        }
        #pragma unroll
        for (int o = 16; o; o >>= 1) {
            s  += __shfl_down_sync(0xffffffffu, s,  o);
            ss += __shfl_down_sync(0xffffffffu, ss, o);
        }
        __shared__ float sh[16];
        const int w = threadIdx.x >> 5, l = threadIdx.x & 31;
        if (l == 0) { sh[w] = s; sh[8 + w] = ss; }
        __syncthreads();
        if (threadIdx.x == 0) {
            float S = 0.f, SS = 0.f;
            #pragma unroll
            for (int i = 0; i < 8; i++) { S += sh[i]; SS += sh[8 + i]; }
            const float mean = S * (1.f / 16384.f);
            const float var  = SS * (1.f / 16384.f) - mean * mean;
            g_mean[bg] = mean;
            g_rstd[bg] = rsqrtf(var + 1e-5f);
        }
    } else {
        const int i = (blockIdx.x - 512) * 256 + threadIdx.x;
        const int NQ = 3 * CH * CH / 2;
        if (i < NQ) {
            float2 v = ((const float2*)qw)[i];
            __half2 h = __floats2half2_rn(v.x, v.y);
            ((uint32_t*)g_Whq)[i] = *(uint32_t*)&h;
        } else {
            const int j = i - NQ;
            float2 v = ((const float2*)pw)[j];
            __half2 h = __floats2half2_rn(v.x, v.y);
            ((uint32_t*)g_Whp)[j] = *(uint32_t*)&h;
        }
    }
}

// ---------------- x pack: GroupNorm + fp16 + transpose -> [b][t][c] -------------
__global__ void x_pack_kernel(const float* __restrict__ x,
                              const float* __restrict__ nw,
                              const float* __restrict__ nb) {
    __shared__ float tile[64][68];
    const int t0 = blockIdx.x * 64, c0 = blockIdx.y * 64, b = blockIdx.z;
    const int tid = threadIdx.x;
    const float* xb = x + (size_t)b * CH * TT;
    #pragma unroll
    for (int it = 0; it < 4; ++it) {
        const int f = tid + it * 256;
        const int cl = f >> 4, t4 = (f & 15) << 2;
        const int c = c0 + cl;
        float4 v = *(const float4*)(xb + (size_t)c * TT + t0 + t4);
        const int bg = (b << 5) + (c >> 4);
        const float w  = nw[c] * g_rstd[bg];
        const float bb = fmaf(-g_mean[bg], w, nb[c]);
        tile[cl][t4 + 0] = fmaf(v.x, w, bb);
        tile[cl][t4 + 1] = fmaf(v.y, w, bb);
        tile[cl][t4 + 2] = fmaf(v.z, w, bb);
        tile[cl][t4 + 3] = fmaf(v.w, w, bb);
    }
    __syncthreads();
    #pragma unroll
    for (int it = 0; it < 4; ++it) {
        const int f = tid + it * 256;
        const int tl = f >> 4, c4 = (f & 15) << 2;
        __half2 h0 = __floats2half2_rn(tile[c4 + 0][tl], tile[c4 + 1][tl]);
        __half2 h1 = __floats2half2_rn(tile[c4 + 2][tl], tile[c4 + 3][tl]);
        const size_t off = ((size_t)b * TT + t0 + tl) * CH + c0 + c4;
        *(uint2*)(g_Xh + off) = make_uint2(*(uint32_t*)&h0, *(uint32_t*)&h1);
    }
}

// ---------------- HMMA GEMM (1-term), 4-stage cp.async ring ----------------------
#define GP 40
#define GSB (128 * GP)
#define GSTG (2 * GSB * 2)
#define GEMM_SMEM (4 * GSTG)
#define VBP 136   // vbuf pitch (halves): quad c-stride 2 rows -> 8 banks apart

template<bool IS_PROJ>
__global__ __launch_bounds__(256, 2)
void hgemm_kernel(const float* __restrict__ bias,
                  const float* __restrict__ resid,
                  float* __restrict__ outp) {
    extern __shared__ __half smh[];
    const uint32_t sb = smem_u32(smh);
    const int tid = threadIdx.x, lane = tid & 31, wid = tid >> 5;
    const int g = lane >> 2, tig = lane & 3;
    const int b = blockIdx.z;
    const int r0 = (IS_PROJ ? blockIdx.y : blockIdx.x) * 128;
    const int c0 = (IS_PROJ ? blockIdx.x : blockIdx.y) * 128;
    const int warp_m = wid >> 2, warp_n = wid & 3;

    const __half *pAh, *pBh;
    if (IS_PROJ) {
        pAh = g_Whp + (size_t)r0 * CH;
        pBh = g_hh + ((size_t)b * TT + c0) * CH;
    } else {
        pAh = g_Xh + ((size_t)b * TT + r0) * CH;
        pBh = g_Whq + (size_t)c0 * CH;
    }

    float acc[4][4][4];
    #pragma unroll
    for (int mi = 0; mi < 4; ++mi)
        #pragma unroll
        for (int ni = 0; ni < 4; ++ni)
            #pragma unroll
            for (int r = 0; r < 4; ++r) acc[mi][ni][r] = 0.f;

    const int aRow = warp_m * 64 + (lane & 15);
    const int aK   = (lane >> 4) << 3;
    const int bRow = warp_n * 32 + (lane & 7) + ((lane >> 4) << 3);
    const int bK   = ((lane >> 3) & 1) << 3;

    auto issue = [&](int ck) {
        const uint32_t st = sb + (ck & 3) * GSTG;
        const int k0 = ck * 32;
        #pragma unroll
        for (int it = 0; it < 2; ++it) {
            const int f = tid + it * 256;
            const int row = f >> 2, sg = (f & 3) << 3;
            const uint32_t da = st + (row * GP + sg) * 2;
            cp16(da,           pAh + (size_t)row * CH + k0 + sg);
            cp16(da + GSB * 2, pBh + (size_t)row * CH + k0 + sg);
        }
    };

    auto compute = [&](int ck) {
        const uint32_t st = sb + (ck & 3) * GSTG;
        const uint32_t aH = st, bH = st + GSB * 2;
        #pragma unroll
        for (int kk = 0; kk < 32; kk += 16) {
            uint32_t afh[4][4];
            #pragma unroll
            for (int mi = 0; mi < 4; ++mi)
                ldsm4(afh[mi], aH + ((aRow + mi * 16) * GP + kk + aK) * 2);
            #pragma unroll
            for (int nj = 0; nj < 2; ++nj) {
                uint32_t bfh[4];
                ldsm4(bfh, bH + ((bRow + nj * 16) * GP + kk + bK) * 2);
                #pragma unroll
                for (int mi = 0; mi < 4; ++mi) {
                    mma16816(acc[mi][nj * 2 + 0], afh[mi], bfh[0], bfh[1]);
                    mma16816(acc[mi][nj * 2 + 1], afh[mi], bfh[2], bfh[3]);
                }
            }
        }
    };

    issue(0); CP_COMMIT();
    issue(1); CP_COMMIT();
    issue(2); CP_COMMIT();
    for (int ck = 0; ck < 16; ++ck) {
        if (ck <= 13) CP_WAIT(2);
        else if (ck == 14) CP_WAIT(1);
        else CP_WAIT(0);
        __syncthreads();
        if (ck < 13) { issue(ck + 3); CP_COMMIT(); }
        compute(ck);
    }

    if (IS_PROJ) {
        const int mbase = r0 + warp_m * 64;
        const int nbase = c0 + warp_n * 32;
        const float* xres = resid + (size_t)b * CH * TT;
        float* ob = outp + (size_t)b * CH * TT;
        #pragma unroll
        for (int mi = 0; mi < 4; ++mi) {
            const int mA = mbase + mi * 16 + g;
            const int mB = mA + 8;
            const float biA = bias[mA], biB = bias[mB];
            #pragma unroll
            for (int ni = 0; ni < 4; ++ni) {
                const int t = nbase + ni * 8 + tig * 2;
                float2 v0, v1;
                v0.x = acc[mi][ni][0] + biA; v0.y = acc[mi][ni][1] + biA;
                v1.x = acc[mi][ni][2] + biB; v1.y = acc[mi][ni][3] + biB;
                float2 r0v = *(const float2*)(xres + (size_t)mA * TT + t);
                float2 r1v = *(const float2*)(xres + (size_t)mB * TT + t);
                v0.x += r0v.x; v0.y += r0v.y;
                v1.x += r1v.x; v1.y += r1v.y;
                *(float2*)(ob + (size_t)mA * TT + t) = v0;
                *(float2*)(ob + (size_t)mB * TT + t) = v1;
            }
        }
    } else {
        // V goes through a smem transpose (vbuf aliases stage 0, disjoint from
        // stages 1-3 that trailing warps may still read); Q/K store directly.
        const int tileIdx = blockIdx.y;
        const bool hasV = (tileIdx % 3) != 0;
        const int voff = (tileIdx % 3 == 1) ? 0 : 64;   // V segment offset in tile
        #pragma unroll
        for (int ni = 0; ni < 4; ++ni) {
            const int m = c0 + warp_n * 32 + ni * 8 + tig * 2;
            const int head = m / 192;
            const int rmod = m - head * 192;
            const int kind = rmod >> 6, c = rmod & 63;
            const int bh = b * NHEAD + head;
            const float b0v = bias[m], b1v = bias[m + 1];
            #pragma unroll
            for (int mi = 0; mi < 4; ++mi) {
                #pragma unroll
                for (int rr = 0; rr < 2; ++rr) {
                    const int tl = warp_m * 64 + mi * 16 + g + rr * 8;
                    const int t = r0 + tl;
                    float v0 = acc[mi][ni][rr * 2 + 0] + b0v;
                    float v1 = acc[mi][ni][rr * 2 + 1] + b1v;
                    if (kind == 0) {
                        v0 *= QSCALE; v1 *= QSCALE;   // fold softmax scale + log2e
                        __half2 h2 = __floats2half2_rn(v0, v1);
                        *(__half2*)(g_Qh + ((size_t)bh * TT + t) * HD + c) = h2;
                    } else if (kind == 1) {
                        __half2 h2 = __floats2half2_rn(v0, v1);
                        *(__half2*)(g_Kh + ((size_t)bh * TT + t) * HD + c) = h2;
                    } else {
                        smh[(c + 0) * VBP + tl] = __float2half_rn(v0);
                        smh[(c + 1) * VBP + tl] = __float2half_rn(v1);
                    }
                }
            }
        }
        if (hasV) {
            __syncthreads();   // uniform branch: all threads participate
            const int headv = (c0 + voff) / 192;
            const int bhv = b * NHEAD + headv;
            // 64 rows x 128 halves, 16B vectors: 1024 uint4 / 256 threads
            #pragma unroll
            for (int i = tid; i < 1024; i += 256) {
                const int row = i >> 4, col = (i & 15) << 3;
                uint4 v = *(const uint4*)(smh + row * VBP + col);
                *(uint4*)(g_Vh + ((size_t)bhv * HD + row) * TT + r0 + col) = v;
            }
        }
    }
}

// ---------------- HMMA flash attention: KV block 128, 2-stage ring, exp2 domain --
// smem halves: Q @0 (128 x AP); stage s @9216 + s*17920: K 128xAP (+0),
//              V 64 x VP (+9216). AP=72, VP=136.
// Ring discipline (2 stages): compute(kb) -> __syncthreads -> issue(kb+2).
// Row-sum l via extra MMA against constant all-ones B fragment (ONES16).
#define AP 72
#define VP 136
#define ASTG (9216 + 8704)                  // 17920 halves per stage
#define ATTN_SMEM ((9216 + 2 * ASTG) * 2)   // 90112 B

__global__ __launch_bounds__(256, 2)
void attn_kernel() {
    extern __shared__ __half sa[];
    const uint32_t sb = smem_u32(sa);
    const int tid = threadIdx.x, lane = tid & 31, wid = tid >> 5;
    const int g = lane >> 2, tig = lane & 3;
    const int tblk = blockIdx.x, head = blockIdx.y, b = blockIdx.z;
    const int bh = b * NHEAD + head;
    const int t0 = tblk * 128;

    {   // Q: 128 rows x 64 halves (group 0)
        const __half* qh = g_Qh + ((size_t)bh * TT + t0) * HD;
        #pragma unroll
        for (int it = 0; it < 4; ++it) {
            const int f = tid + it * 256;
            const int row = f >> 3, sg = (f & 7) << 3;
            cp16(sb + (row * AP + sg) * 2, qh + (size_t)row * HD + sg);
        }
    }
    auto issueKV = [&](int kb) {
        const uint32_t st = sb + (9216 + (kb & 1) * ASTG) * 2;
        const int s0 = kb * 128;
        const __half* kh = g_Kh + ((size_t)bh * TT + s0) * HD;
        const __half* vh = g_Vh + (size_t)bh * HD * TT + s0;
        #pragma unroll
        for (int it = 0; it < 4; ++it) {
            const int f = tid + it * 256;
            const int kr = f >> 3, ksg = (f & 7) << 3;        // K: 128 rows x 64
            cp16(st + (kr * AP + ksg) * 2, kh + (size_t)kr * HD + ksg);
            const int vr = f >> 4, vsg = (f & 15) << 3;       // V: 64 rows x 128
            cp16(st + (9216 + vr * VP + vsg) * 2, vh + (size_t)vr * TT + vsg);
        }
    };

    issueKV(0); CP_COMMIT();
    issueKV(1); CP_COMMIT();

    const int qRow = wid * 16 + (lane & 15);
    const int qK   = (lane >> 4) << 3;
    const int nRow = (lane & 7) + ((lane >> 4) << 3);
    const int nK   = ((lane >> 3) & 1) << 3;

    float m_i0 = -1e30f, m_i1 = -1e30f;
    float oacc[8][4], lacc[4];
    #pragma unroll
    for (int nc = 0; nc < 8; ++nc)
        #pragma unroll
        for (int r = 0; r < 4; ++r) oacc[nc][r] = 0.f;
    #pragma unroll
    for (int r = 0; r < 4; ++r) lacc[r] = 0.f;

    for (int kb = 0; kb < 8; ++kb) {
        if (kb < 7) CP_WAIT(1); else CP_WAIT(0);
        __syncthreads();
        const uint32_t st = sb + (9216 + (kb & 1) * ASTG) * 2;

        // ---- S = Q K^T over 128 s-cols (Q pre-scaled into exp2 domain)
        float sacc[16][4];
        #pragma unroll
        for (int ni = 0; ni < 16; ++ni)
            #pragma unroll
            for (int r = 0; r < 4; ++r) sacc[ni][r] = 0.f;

        #pragma unroll
        for (int ks = 0; ks < 4; ++ks) {
            uint32_t ah[4];
            ldsm4(ah, sb + ((qRow * AP) + ks * 16 + qK) * 2);
            #pragma unroll
            for (int nj = 0; nj < 8; ++nj) {
                uint32_t kb4[4];
                ldsm4(kb4, st + (((nj * 16 + nRow) * AP) + ks * 16 + nK) * 2);
                mma16816(sacc[nj * 2 + 0], ah, kb4[0], kb4[1]);
                mma16816(sacc[nj * 2 + 1], ah, kb4[2], kb4[3]);
            }
        }

        // ---- online softmax in exp2 domain (rows g and g+8)
        float mx0 = -1e30f, mx1 = -1e30f;
        #pragma unroll
        for (int ni = 0; ni < 16; ++ni) {
            mx0 = fmaxf(mx0, fmaxf(sacc[ni][0], sacc[ni][1]));
            mx1 = fmaxf(mx1, fmaxf(sacc[ni][2], sacc[ni][3]));
        }
        mx0 = fmaxf(mx0, __shfl_xor_sync(0xffffffffu, mx0, 1));
        mx0 = fmaxf(mx0, __shfl_xor_sync(0xffffffffu, mx0, 2));
        mx1 = fmaxf(mx1, __shfl_xor_sync(0xffffffffu, mx1, 1));
        mx1 = fmaxf(mx1, __shfl_xor_sync(0xffffffffu, mx1, 2));
        const float mn0 = fmaxf(m_i0, mx0), mn1 = fmaxf(m_i1, mx1);
        const float c0 = ex2(m_i0 - mn0), c1 = ex2(m_i1 - mn1);
        m_i0 = mn0; m_i1 = mn1;
        // exp (fp32 MUFU) -> packed P fragments aliased into sacc[ni][0..1]
        #pragma unroll
        for (int ni = 0; ni < 16; ++ni) {
            const float p0 = ex2(sacc[ni][0] - mn0);
            const float p1 = ex2(sacc[ni][1] - mn0);
            const float p2 = ex2(sacc[ni][2] - mn1);
            const float p3 = ex2(sacc[ni][3] - mn1);
            __half2 h0 = __floats2half2_rn(p0, p1);
            __half2 h1 = __floats2half2_rn(p2, p3);
            sacc[ni][0] = __uint_as_float(*reinterpret_cast<uint32_t*>(&h0));
            sacc[ni][1] = __uint_as_float(*reinterpret_cast<uint32_t*>(&h1));
        }
        #pragma unroll
        for (int nc = 0; nc < 8; ++nc) {
            oacc[nc][0] *= c0; oacc[nc][1] *= c0;
            oacc[nc][2] *= c1; oacc[nc][3] *= c1;
        }
        lacc[0] *= c0; lacc[1] *= c0; lacc[2] *= c1; lacc[3] *= c1;

        // ---- O += P Vh^T, l += P·1 (s-dim 128 = 8 k-steps of 16)
        #pragma unroll
        for (int ks = 0; ks < 8; ++ks) {
            const uint32_t pa[4] = {
                __float_as_uint(sacc[2 * ks][0]),     __float_as_uint(sacc[2 * ks][1]),
                __float_as_uint(sacc[2 * ks + 1][0]), __float_as_uint(sacc[2 * ks + 1][1]) };
            #pragma unroll
            for (int nj = 0; nj < 4; ++nj) {
                uint32_t vb4[4];
                ldsm4(vb4, st + ((9216 + (nj * 16 + nRow) * VP) + ks * 16 + nK) * 2);
                mma16816(oacc[nj * 2 + 0], pa, vb4[0], vb4[1]);
                mma16816(oacc[nj * 2 + 1], pa, vb4[2], vb4[3]);
            }
            mma16816(lacc, pa, ONES16, ONES16);   // row sums
        }

        // all reads of stage (kb & 1) complete before it is overwritten
        __syncthreads();
        if (kb < 6) { issueKV(kb + 2); CP_COMMIT(); }
    }

    // ---- epilogue: store fp16 h, [b][t][c]
    const float inv0 = 1.f / lacc[0], inv1 = 1.f / lacc[2];
    #pragma unroll
    for (int nc = 0; nc < 8; ++nc) {
        const size_t off0 = ((size_t)b * TT + t0 + wid * 16 + g) * CH
                          + head * 64 + nc * 8 + tig * 2;
        __half2 h0 = __floats2half2_rn(oacc[nc][0] * inv0, oacc[nc][1] * inv0);
        *(__half2*)(g_hh + off0) = h0;
        const size_t off1 = off0 + (size_t)8 * CH;
        __half2 h1 = __floats2half2_rn(oacc[nc][2] * inv1, oacc[nc][3] * inv1);
        *(__half2*)(g_hh + off1) = h1;
    }
}

// ---------------- launch ----------------------------------------------------------
extern "C" void kernel_launch(void* const* d_in, const int* in_sizes, int n_in,
                              void* d_out, int out_size) {
    const float* x    = (const float*)d_in[0];
    const float* nw   = (const float*)d_in[1];
    const float* nb   = (const float*)d_in[2];
    const float* qkvw = (const float*)d_in[3];
    const float* qkvb = (const float*)d_in[4];
    const float* pw   = (const float*)d_in[5];
    const float* pb   = (const float*)d_in[6];
    float* out = (float*)d_out;

    cudaFuncSetAttribute(hgemm_kernel<false>,
                         cudaFuncAttributeMaxDynamicSharedMemorySize, GEMM_SMEM);
    cudaFuncSetAttribute(hgemm_kernel<true>,
                         cudaFuncAttributeMaxDynamicSharedMemorySize, GEMM_SMEM);
    cudaFuncSetAttribute(attn_kernel,
                         cudaFuncAttributeMaxDynamicSharedMemorySize, ATTN_SMEM);

    init_pack_kernel<<<512 + 2048, 256>>>(x, qkvw, pw);
    x_pack_kernel<<<dim3(16, 8, 16), 256>>>(x, nw, nb);
    hgemm_kernel<false><<<dim3(8, 12, BATCH), 256, GEMM_SMEM>>>(qkvb, nullptr, nullptr);
    attn_kernel<<<dim3(8, NHEAD, BATCH), 256, ATTN_SMEM>>>();
    hgemm_kernel<true><<<dim3(8, 4, BATCH), 256, GEMM_SMEM>>>(pb, x, out);
}

// round 17
// speedup vs baseline: 1.0929x; 1.0484x over previous
#include <cuda_runtime.h>
#include <cuda_fp16.h>
#include <stdint.h>
#include <math.h>

#define BATCH 16
#define CH    512
#define TT    1024
#define NHEAD 8
#define BHD   (BATCH * NHEAD)
#define HD    64

// Q pre-scale: hd^-0.5 (=0.125) * log2(e), so softmax runs in exp2 domain
#define QSCALE 0.1803368801111f
// fp16 {1.0, 1.0} — B fragment of an all-ones tile
#define ONES16 0x3C003C00u

// ---------------- scratch ----------------------------------------------------
__device__ float g_mean[BATCH * 32];
__device__ float g_rstd[BATCH * 32];
__device__ __half g_Xh[(size_t)BATCH * TT * CH];
__device__ __half g_Whq[3 * CH * CH];
__device__ __half g_Whp[CH * CH];
__device__ __half g_Qh[(size_t)BHD * TT * HD];
__device__ __half g_Kh[(size_t)BHD * TT * HD];
__device__ __half g_Vh[(size_t)BHD * HD * TT];
__device__ __half g_hh[(size_t)BATCH * TT * CH];

// ---------------- helpers ------------------------------------------------------
__device__ __forceinline__ float ex2(float x) {
    float y;
    asm("ex2.approx.ftz.f32 %0, %1;" : "=f"(y) : "f"(x));
    return y;
}
__device__ __forceinline__ void mma16816(float c[4], const uint32_t a[4],
                                         uint32_t b0, uint32_t b1) {
    asm volatile(
        "mma.sync.aligned.m16n8k16.row.col.f32.f16.f16.f32 "
        "{%0,%1,%2,%3}, {%4,%5,%6,%7}, {%8,%9}, {%0,%1,%2,%3};"
        : "+f"(c[0]), "+f"(c[1]), "+f"(c[2]), "+f"(c[3])
        : "r"(a[0]), "r"(a[1]), "r"(a[2]), "r"(a[3]), "r"(b0), "r"(b1));
}
__device__ __forceinline__ void ldsm4(uint32_t r[4], uint32_t addr) {
    asm volatile("ldmatrix.sync.aligned.m8n8.x4.shared.b16 {%0,%1,%2,%3}, [%4];"
                 : "=r"(r[0]), "=r"(r[1]), "=r"(r[2]), "=r"(r[3]) : "r"(addr));
}
__device__ __forceinline__ uint32_t smem_u32(const void* p) {
    uint32_t a;
    asm("{ .reg .u64 t; cvta.to.shared.u64 t, %1; cvt.u32.u64 %0, t; }"
        : "=r"(a) : "l"(p));
    return a;
}
__device__ __forceinline__ void cp16(uint32_t d, const void* s) {
    asm volatile("cp.async.cg.shared.global [%0], [%1], 16;" :: "r"(d), "l"(s));
}
#define CP_COMMIT() asm volatile("cp.async.commit_group;" ::: "memory")
#define CP_WAIT(n)  asm volatile("cp.async.wait_group %0;" :: "n"(n) : "memory")

// ---------------- init: GroupNorm stats (blocks 0..511) + weight fp16 pack ------
__global__ void init_pack_kernel(const float* __restrict__ x,
                                 const float* __restrict__ qw,
                                 const float* __restrict__ pw) {
    if (blockIdx.x < 512) {
        const int bg = blockIdx.x;
        const float4* base = (const float4*)(x + (size_t)bg * 16 * TT);
        float s = 0.f, ss = 0.f;
        for (int i = threadIdx.x; i < 4096; i += 256) {
            float4 v = base[i];
            s  += v.x + v.y + v.z + v.w;
            ss += v.x*v.x + v.y*v.y + v.z*v.z + v.w*v.w;
        }
        #pragma unroll
        for (int o = 16; o; o >>= 1) {
            s  += __shfl_down_sync(0xffffffffu, s,  o);
            ss += __shfl_down_sync(0xffffffffu, ss, o);
        }
        __shared__ float sh[16];
        const int w = threadIdx.x >> 5, l = threadIdx.x & 31;
        if (l == 0) { sh[w] = s; sh[8 + w] = ss; }
        __syncthreads();
        if (threadIdx.x == 0) {
            float S = 0.f, SS = 0.f;
            #pragma unroll
            for (int i = 0; i < 8; i++) { S += sh[i]; SS += sh[8 + i]; }
            const float mean = S * (1.f / 16384.f);
            const float var  = SS * (1.f / 16384.f) - mean * mean;
            g_mean[bg] = mean;
            g_rstd[bg] = rsqrtf(var + 1e-5f);
        }
    } else {
        const int i = (blockIdx.x - 512) * 256 + threadIdx.x;
        const int NQ = 3 * CH * CH / 2;
        if (i < NQ) {
            float2 v = ((const float2*)qw)[i];
            __half2 h = __floats2half2_rn(v.x, v.y);
            ((uint32_t*)g_Whq)[i] = *(uint32_t*)&h;
        } else {
            const int j = i - NQ;
            float2 v = ((const float2*)pw)[j];
            __half2 h = __floats2half2_rn(v.x, v.y);
            ((uint32_t*)g_Whp)[j] = *(uint32_t*)&h;
        }
    }
}

// ---------------- x pack: GroupNorm + fp16 + transpose -> [b][t][c] -------------
__global__ void x_pack_kernel(const float* __restrict__ x,
                              const float* __restrict__ nw,
                              const float* __restrict__ nb) {
    __shared__ float tile[64][68];
    const int t0 = blockIdx.x * 64, c0 = blockIdx.y * 64, b = blockIdx.z;
    const int tid = threadIdx.x;
    const float* xb = x + (size_t)b * CH * TT;
    #pragma unroll
    for (int it = 0; it < 4; ++it) {
        const int f = tid + it * 256;
        const int cl = f >> 4, t4 = (f & 15) << 2;
        const int c = c0 + cl;
        float4 v = *(const float4*)(xb + (size_t)c * TT + t0 + t4);
        const int bg = (b << 5) + (c >> 4);
        const float w  = nw[c] * g_rstd[bg];
        const float bb = fmaf(-g_mean[bg], w, nb[c]);
        tile[cl][t4 + 0] = fmaf(v.x, w, bb);
        tile[cl][t4 + 1] = fmaf(v.y, w, bb);
        tile[cl][t4 + 2] = fmaf(v.z, w, bb);
        tile[cl][t4 + 3] = fmaf(v.w, w, bb);
    }
    __syncthreads();
    #pragma unroll
    for (int it = 0; it < 4; ++it) {
        const int f = tid + it * 256;
        const int tl = f >> 4, c4 = (f & 15) << 2;
        __half2 h0 = __floats2half2_rn(tile[c4 + 0][tl], tile[c4 + 1][tl]);
        __half2 h1 = __floats2half2_rn(tile[c4 + 2][tl], tile[c4 + 3][tl]);
        const size_t off = ((size_t)b * TT + t0 + tl) * CH + c0 + c4;
        *(uint2*)(g_Xh + off) = make_uint2(*(uint32_t*)&h0, *(uint32_t*)&h1);
    }
}

// ---------------- HMMA GEMM (1-term), chunk 64, 3-stage cp.async ring -----------
#define GP 72                              // smem pitch (halves) for 64-wide rows
#define GSB (128 * GP)                     // 9216 halves per array
#define GSTG (2 * GSB * 2)                 // 36864 B per stage (A, B)
#define GEMM_SMEM (3 * GSTG)               // 110592 B
#define VBP 136   // vbuf pitch (halves); vbuf aliases stage 0 (final reads hit stage 1)

template<bool IS_PROJ>
__global__ __launch_bounds__(256, 2)
void hgemm_kernel(const float* __restrict__ bias,
                  const float* __restrict__ resid,
                  float* __restrict__ outp) {
    extern __shared__ __half smh[];
    const uint32_t sb = smem_u32(smh);
    const int tid = threadIdx.x, lane = tid & 31, wid = tid >> 5;
    const int g = lane >> 2, tig = lane & 3;
    const int b = blockIdx.z;
    const int r0 = (IS_PROJ ? blockIdx.y : blockIdx.x) * 128;
    const int c0 = (IS_PROJ ? blockIdx.x : blockIdx.y) * 128;
    const int warp_m = wid >> 2, warp_n = wid & 3;

    const __half *pAh, *pBh;
    if (IS_PROJ) {
        pAh = g_Whp + (size_t)r0 * CH;
        pBh = g_hh + ((size_t)b * TT + c0) * CH;
    } else {
        pAh = g_Xh + ((size_t)b * TT + r0) * CH;
        pBh = g_Whq + (size_t)c0 * CH;
    }

    float acc[4][4][4];
    #pragma unroll
    for (int mi = 0; mi < 4; ++mi)
        #pragma unroll
        for (int ni = 0; ni < 4; ++ni)
            #pragma unroll
            for (int r = 0; r < 4; ++r) acc[mi][ni][r] = 0.f;

    const int aRow = warp_m * 64 + (lane & 15);
    const int aK   = (lane >> 4) << 3;
    const int bRow = warp_n * 32 + (lane & 7) + ((lane >> 4) << 3);
    const int bK   = ((lane >> 3) & 1) << 3;

    auto issue = [&](int ck) {
        const uint32_t st = sb + (ck % 3) * GSTG;
        const int k0 = ck * 64;
        #pragma unroll
        for (int it = 0; it < 4; ++it) {
            const int f = tid + it * 256;
            const int row = f >> 3, sg = (f & 7) << 3;   // row 0..127, sg 0..56
            const uint32_t da = st + (row * GP + sg) * 2;
            cp16(da,           pAh + (size_t)row * CH + k0 + sg);
            cp16(da + GSB * 2, pBh + (size_t)row * CH + k0 + sg);
        }
    };

    auto compute = [&](int ck) {
        const uint32_t st = sb + (ck % 3) * GSTG;
        const uint32_t aH = st, bH = st + GSB * 2;
        #pragma unroll
        for (int kk = 0; kk < 64; kk += 16) {
            uint32_t afh[4][4];
            #pragma unroll
            for (int mi = 0; mi < 4; ++mi)
                ldsm4(afh[mi], aH + ((aRow + mi * 16) * GP + kk + aK) * 2);
            #pragma unroll
            for (int nj = 0; nj < 2; ++nj) {
                uint32_t bfh[4];
                ldsm4(bfh, bH + ((bRow + nj * 16) * GP + kk + bK) * 2);
                #pragma unroll
                for (int mi = 0; mi < 4; ++mi) {
                    mma16816(acc[mi][nj * 2 + 0], afh[mi], bfh[0], bfh[1]);
                    mma16816(acc[mi][nj * 2 + 1], afh[mi], bfh[2], bfh[3]);
                }
            }
        }
    };

    issue(0); CP_COMMIT();
    issue(1); CP_COMMIT();
    for (int ck = 0; ck < 8; ++ck) {
        if (ck < 7) CP_WAIT(1); else CP_WAIT(0);
        __syncthreads();
        if (ck < 6) { issue(ck + 2); CP_COMMIT(); }
        compute(ck);
    }

    if (IS_PROJ) {
        const int mbase = r0 + warp_m * 64;
        const int nbase = c0 + warp_n * 32;
        const float* xres = resid + (size_t)b * CH * TT;
        float* ob = outp + (size_t)b * CH * TT;
        #pragma unroll
        for (int mi = 0; mi < 4; ++mi) {
            const int mA = mbase + mi * 16 + g;
            const int mB = mA + 8;
            const float biA = bias[mA], biB = bias[mB];
            #pragma unroll
            for (int ni = 0; ni < 4; ++ni) {
                const int t = nbase + ni * 8 + tig * 2;
                float2 v0, v1;
                v0.x = acc[mi][ni][0] + biA; v0.y = acc[mi][ni][1] + biA;
                v1.x = acc[mi][ni][2] + biB; v1.y = acc[mi][ni][3] + biB;
                float2 r0v = *(const float2*)(xres + (size_t)mA * TT + t);
                float2 r1v = *(const float2*)(xres + (size_t)mB * TT + t);
                v0.x += r0v.x; v0.y += r0v.y;
                v1.x += r1v.x; v1.y += r1v.y;
                *(float2*)(ob + (size_t)mA * TT + t) = v0;
                *(float2*)(ob + (size_t)mB * TT + t) = v1;
            }
        }
    } else {
        // V goes through a smem transpose (vbuf aliases stage 0; final compute
        // reads stage 7%3=1, disjoint); Q/K store directly.
        const int tileIdx = blockIdx.y;
        const bool hasV = (tileIdx % 3) != 0;
        const int voff = (tileIdx % 3 == 1) ? 0 : 64;
        #pragma unroll
        for (int ni = 0; ni < 4; ++ni) {
            const int m = c0 + warp_n * 32 + ni * 8 + tig * 2;
            const int head = m / 192;
            const int rmod = m - head * 192;
            const int kind = rmod >> 6, c = rmod & 63;
            const int bh = b * NHEAD + head;
            const float b0v = bias[m], b1v = bias[m + 1];
            #pragma unroll
            for (int mi = 0; mi < 4; ++mi) {
                #pragma unroll
                for (int rr = 0; rr < 2; ++rr) {
                    const int tl = warp_m * 64 + mi * 16 + g + rr * 8;
                    const int t = r0 + tl;
                    float v0 = acc[mi][ni][rr * 2 + 0] + b0v;
                    float v1 = acc[mi][ni][rr * 2 + 1] + b1v;
                    if (kind == 0) {
                        v0 *= QSCALE; v1 *= QSCALE;   // fold softmax scale + log2e
                        __half2 h2 = __floats2half2_rn(v0, v1);
                        *(__half2*)(g_Qh + ((size_t)bh * TT + t) * HD + c) = h2;
                    } else if (kind == 1) {
                        __half2 h2 = __floats2half2_rn(v0, v1);
                        *(__half2*)(g_Kh + ((size_t)bh * TT + t) * HD + c) = h2;
                    } else {
                        smh[(c + 0) * VBP + tl] = __float2half_rn(v0);
                        smh[(c + 1) * VBP + tl] = __float2half_rn(v1);
                    }
                }
            }
        }
        if (hasV) {
            __syncthreads();   // uniform branch: all threads participate
            const int headv = (c0 + voff) / 192;
            const int bhv = b * NHEAD + headv;
            #pragma unroll
            for (int i = tid; i < 1024; i += 256) {
                const int row = i >> 4, col = (i & 15) << 3;
                uint4 v = *(const uint4*)(smh + row * VBP + col);
                *(uint4*)(g_Vh + ((size_t)bhv * HD + row) * TT + r0 + col) = v;
            }
        }
    }
}

// ---------------- HMMA flash attention: KV block 128, 2-stage ring, exp2 domain --
// smem halves: Q @0 (128 x AP); stage s @9216 + s*17920: K 128xAP (+0),
//              V 64 x VP (+9216). AP=72, VP=136.
// Ring discipline (2 stages): compute(kb) -> __syncthreads -> issue(kb+2).
// Row-sum l via extra MMA against constant all-ones B fragment (ONES16).
#define AP 72
#define VP 136
#define ASTG (9216 + 8704)                  // 17920 halves per stage
#define ATTN_SMEM ((9216 + 2 * ASTG) * 2)   // 90112 B

__global__ __launch_bounds__(256, 2)
void attn_kernel() {
    extern __shared__ __half sa[];
    const uint32_t sb = smem_u32(sa);
    const int tid = threadIdx.x, lane = tid & 31, wid = tid >> 5;
    const int g = lane >> 2, tig = lane & 3;
    const int tblk = blockIdx.x, head = blockIdx.y, b = blockIdx.z;
    const int bh = b * NHEAD + head;
    const int t0 = tblk * 128;

    {   // Q: 128 rows x 64 halves (group 0)
        const __half* qh = g_Qh + ((size_t)bh * TT + t0) * HD;
        #pragma unroll
        for (int it = 0; it < 4; ++it) {
            const int f = tid + it * 256;
            const int row = f >> 3, sg = (f & 7) << 3;
            cp16(sb + (row * AP + sg) * 2, qh + (size_t)row * HD + sg);
        }
    }
    auto issueKV = [&](int kb) {
        const uint32_t st = sb + (9216 + (kb & 1) * ASTG) * 2;
        const int s0 = kb * 128;
        const __half* kh = g_Kh + ((size_t)bh * TT + s0) * HD;
        const __half* vh = g_Vh + (size_t)bh * HD * TT + s0;
        #pragma unroll
        for (int it = 0; it < 4; ++it) {
            const int f = tid + it * 256;
            const int kr = f >> 3, ksg = (f & 7) << 3;        // K: 128 rows x 64
            cp16(st + (kr * AP + ksg) * 2, kh + (size_t)kr * HD + ksg);
            const int vr = f >> 4, vsg = (f & 15) << 3;       // V: 64 rows x 128
            cp16(st + (9216 + vr * VP + vsg) * 2, vh + (size_t)vr * TT + vsg);
        }
    };

    issueKV(0); CP_COMMIT();
    issueKV(1); CP_COMMIT();

    const int qRow = wid * 16 + (lane & 15);
    const int qK   = (lane >> 4) << 3;
    const int nRow = (lane & 7) + ((lane >> 4) << 3);
    const int nK   = ((lane >> 3) & 1) << 3;

    float m_i0 = -1e30f, m_i1 = -1e30f;
    float oacc[8][4], lacc[4];
    #pragma unroll
    for (int nc = 0; nc < 8; ++nc)
        #pragma unroll
        for (int r = 0; r < 4; ++r) oacc[nc][r] = 0.f;
    #pragma unroll
    for (int r = 0; r < 4; ++r) lacc[r] = 0.f;

    for (int kb = 0; kb < 8; ++kb) {
        if (kb < 7) CP_WAIT(1); else CP_WAIT(0);
        __syncthreads();
        const uint32_t st = sb + (9216 + (kb & 1) * ASTG) * 2;

        // ---- S = Q K^T over 128 s-cols (Q pre-scaled into exp2 domain)
        float sacc[16][4];
        #pragma unroll
        for (int ni = 0; ni < 16; ++ni)
            #pragma unroll
            for (int r = 0; r < 4; ++r) sacc[ni][r] = 0.f;

        #pragma unroll
        for (int ks = 0; ks < 4; ++ks) {
            uint32_t ah[4];
            ldsm4(ah, sb + ((qRow * AP) + ks * 16 + qK) * 2);
            #pragma unroll
            for (int nj = 0; nj < 8; ++nj) {
                uint32_t kb4[4];
                ldsm4(kb4, st + (((nj * 16 + nRow) * AP) + ks * 16 + nK) * 2);
                mma16816(sacc[nj * 2 + 0], ah, kb4[0], kb4[1]);
                mma16816(sacc[nj * 2 + 1], ah, kb4[2], kb4[3]);
            }
        }

        // ---- online softmax in exp2 domain (rows g and g+8)
        float mx0 = -1e30f, mx1 = -1e30f;
        #pragma unroll
        for (int ni = 0; ni < 16; ++ni) {
            mx0 = fmaxf(mx0, fmaxf(sacc[ni][0], sacc[ni][1]));
            mx1 = fmaxf(mx1, fmaxf(sacc[ni][2], sacc[ni][3]));
        }
        mx0 = fmaxf(mx0, __shfl_xor_sync(0xffffffffu, mx0, 1));
        mx0 = fmaxf(mx0, __shfl_xor_sync(0xffffffffu, mx0, 2));
        mx1 = fmaxf(mx1, __shfl_xor_sync(0xffffffffu, mx1, 1));
        mx1 = fmaxf(mx1, __shfl_xor_sync(0xffffffffu, mx1, 2));
        const float mn0 = fmaxf(m_i0, mx0), mn1 = fmaxf(m_i1, mx1);
        const float c0 = ex2(m_i0 - mn0), c1 = ex2(m_i1 - mn1);
        m_i0 = mn0; m_i1 = mn1;
        // exp (fp32 MUFU) -> packed P fragments aliased into sacc[ni][0..1]
        #pragma unroll
        for (int ni = 0; ni < 16; ++ni) {
            const float p0 = ex2(sacc[ni][0] - mn0);
            const float p1 = ex2(sacc[ni][1] - mn0);
            const float p2 = ex2(sacc[ni][2] - mn1);
            const float p3 = ex2(sacc[ni][3] - mn1);
            __half2 h0 = __floats2half2_rn(p0, p1);
            __half2 h1 = __floats2half2_rn(p2, p3);
            sacc[ni][0] = __uint_as_float(*reinterpret_cast<uint32_t*>(&h0));
            sacc[ni][1] = __uint_as_float(*reinterpret_cast<uint32_t*>(&h1));
        }
        #pragma unroll
        for (int nc = 0; nc < 8; ++nc) {
            oacc[nc][0] *= c0; oacc[nc][1] *= c0;
            oacc[nc][2] *= c1; oacc[nc][3] *= c1;
        }
        lacc[0] *= c0; lacc[1] *= c0; lacc[2] *= c1; lacc[3] *= c1;

        // ---- O += P Vh^T, l += P·1 (s-dim 128 = 8 k-steps of 16)
        #pragma unroll
        for (int ks = 0; ks < 8; ++ks) {
            const uint32_t pa[4] = {
                __float_as_uint(sacc[2 * ks][0]),     __float_as_uint(sacc[2 * ks][1]),
                __float_as_uint(sacc[2 * ks + 1][0]), __float_as_uint(sacc[2 * ks + 1][1]) };
            #pragma unroll
            for (int nj = 0; nj < 4; ++nj) {
                uint32_t vb4[4];
                ldsm4(vb4, st + ((9216 + (nj * 16 + nRow) * VP) + ks * 16 + nK) * 2);
                mma16816(oacc[nj * 2 + 0], pa, vb4[0], vb4[1]);
                mma16816(oacc[nj * 2 + 1], pa, vb4[2], vb4[3]);
            }
            mma16816(lacc, pa, ONES16, ONES16);   // row sums
        }

        // all reads of stage (kb & 1) complete before it is overwritten
        __syncthreads();
        if (kb < 6) { issueKV(kb + 2); CP_COMMIT(); }
    }

    // ---- epilogue: store fp16 h, [b][t][c]
    const float inv0 = 1.f / lacc[0], inv1 = 1.f / lacc[2];
    #pragma unroll
    for (int nc = 0; nc < 8; ++nc) {
        const size_t off0 = ((size_t)b * TT + t0 + wid * 16 + g) * CH
                          + head * 64 + nc * 8 + tig * 2;
        __half2 h0 = __floats2half2_rn(oacc[nc][0] * inv0, oacc[nc][1] * inv0);
        *(__half2*)(g_hh + off0) = h0;
        const size_t off1 = off0 + (size_t)8 * CH;
        __half2 h1 = __floats2half2_rn(oacc[nc][2] * inv1, oacc[nc][3] * inv1);
        *(__half2*)(g_hh + off1) = h1;
    }
}

// ---------------- launch ----------------------------------------------------------
extern "C" void kernel_launch(void* const* d_in, const int* in_sizes, int n_in,
                              void* d_out, int out_size) {
    const float* x    = (const float*)d_in[0];
    const float* nw   = (const float*)d_in[1];
    const float* nb   = (const float*)d_in[2];
    const float* qkvw = (const float*)d_in[3];
    const float* qkvb = (const float*)d_in[4];
    const float* pw   = (const float*)d_in[5];
    const float* pb   = (const float*)d_in[6];
    float* out = (float*)d_out;

    cudaFuncSetAttribute(hgemm_kernel<false>,
                         cudaFuncAttributeMaxDynamicSharedMemorySize, GEMM_SMEM);
    cudaFuncSetAttribute(hgemm_kernel<true>,
                         cudaFuncAttributeMaxDynamicSharedMemorySize, GEMM_SMEM);
    cudaFuncSetAttribute(attn_kernel,
                         cudaFuncAttributeMaxDynamicSharedMemorySize, ATTN_SMEM);

    init_pack_kernel<<<512 + 2048, 256>>>(x, qkvw, pw);
    x_pack_kernel<<<dim3(16, 8, 16), 256>>>(x, nw, nb);
    hgemm_kernel<false><<<dim3(8, 12, BATCH), 256, GEMM_SMEM>>>(qkvb, nullptr, nullptr);
    attn_kernel<<<dim3(8, NHEAD, BATCH), 256, ATTN_SMEM>>>();
    hgemm_kernel<true><<<dim3(8, 4, BATCH), 256, GEMM_SMEM>>>(pb, x, out);
}